// round 2
// baseline (speedup 1.0000x reference)
#include <cuda_runtime.h>
#include <cuda_bf16.h>
#include <math.h>

// ---- problem constants (BEVDepth config) ----
#define HFm 16
#define WFm 44
#define DEPTH 112
#define CCH 80
#define NCAM 6
#define NXv 128
#define NYv 128
#define HW (HFm * WFm)

// per-camera params: inv(post_rots)[9], post_trans[3], (rots@inv(intrins))[9], trans[3]
__device__ float g_cam[NCAM][24];

__device__ __forceinline__ void inv3x3(const float* a, float* o) {
    float a00=a[0],a01=a[1],a02=a[2];
    float a10=a[3],a11=a[4],a12=a[5];
    float a20=a[6],a21=a[7],a22=a[8];
    float c00 =  (a11*a22 - a12*a21);
    float c01 = -(a10*a22 - a12*a20);
    float c02 =  (a10*a21 - a11*a20);
    float det = a00*c00 + a01*c01 + a02*c02;
    float id = 1.0f / det;
    o[0] =  (a11*a22 - a12*a21) * id;
    o[1] =  (a02*a21 - a01*a22) * id;
    o[2] =  (a01*a12 - a02*a11) * id;
    o[3] =  (a12*a20 - a10*a22) * id;
    o[4] =  (a00*a22 - a02*a20) * id;
    o[5] =  (a02*a10 - a00*a12) * id;
    o[6] =  (a10*a21 - a11*a20) * id;
    o[7] =  (a01*a20 - a00*a21) * id;
    o[8] =  (a00*a11 - a01*a10) * id;
}

__global__ void prep_cams(const float* __restrict__ rots,
                          const float* __restrict__ trans,
                          const float* __restrict__ intrins,
                          const float* __restrict__ post_rots,
                          const float* __restrict__ post_trans) {
    int n = threadIdx.x;
    if (n >= NCAM) return;
    float iP[9], iK[9];
    inv3x3(post_rots + n * 9, iP);
    inv3x3(intrins  + n * 9, iK);
    const float* R = rots + n * 9;
    float* cm = g_cam[n];
    #pragma unroll
    for (int i = 0; i < 9; i++) cm[i] = iP[i];
    #pragma unroll
    for (int i = 0; i < 3; i++) cm[9 + i] = post_trans[n * 3 + i];
    // M = R @ iK
    #pragma unroll
    for (int i = 0; i < 3; i++)
        #pragma unroll
        for (int j = 0; j < 3; j++) {
            float s = 0.f;
            #pragma unroll
            for (int k = 0; k < 3; k++) s += R[i * 3 + k] * iK[k * 3 + j];
            cm[12 + i * 3 + j] = s;
        }
    #pragma unroll
    for (int i = 0; i < 3; i++) cm[21 + i] = trans[n * 3 + i];
}

// One block per camera ray (n, h, w). 128 threads.
// Fused: softmax over D, feature vector to shared, geometry+validity,
// compact valid depth bins, balanced (point x channel) atomic scatter.
__global__ void __launch_bounds__(128)
lss_scatter(const float* __restrict__ depth_digit,
            const float* __restrict__ img_feat,
            float* __restrict__ out) {
    int idx = blockIdx.x;
    int w = idx % WFm;
    int h = (idx / WFm) % HFm;
    int n = idx / (WFm * HFm);
    int tid = threadIdx.x;

    __shared__ float sred[128];
    __shared__ float sfeat[CCH];
    __shared__ float plist[DEPTH];
    __shared__ int   vlist[DEPTH];
    __shared__ float scam[24];
    __shared__ int   cnt;

    if (tid == 0) cnt = 0;
    if (tid < 24) scam[tid] = g_cam[n][tid];

    // load depth logits for this ray
    float myv = -1e30f;
    if (tid < DEPTH)
        myv = depth_digit[(n * DEPTH + tid) * HW + h * WFm + w];

    // block max
    sred[tid] = myv;
    __syncthreads();
    #pragma unroll
    for (int s = 64; s > 0; s >>= 1) {
        if (tid < s) sred[tid] = fmaxf(sred[tid], sred[tid + s]);
        __syncthreads();
    }
    float mx = sred[0];
    __syncthreads();

    float e = (tid < DEPTH) ? __expf(myv - mx) : 0.f;
    sred[tid] = e;
    __syncthreads();
    #pragma unroll
    for (int s = 64; s > 0; s >>= 1) {
        if (tid < s) sred[tid] += sred[tid + s];
        __syncthreads();
    }
    float inv_sum = 1.0f / sred[0];

    // feature vector for this ray
    if (tid < CCH)
        sfeat[tid] = img_feat[(n * CCH + tid) * HW + h * WFm + w];

    // geometry per depth bin
    if (tid < DEPTH) {
        float xpix = (float)((double)w * (703.0 / 43.0));  // linspace(0, 703, 44)
        float ypix = (float)h * 17.0f;                      // linspace(0, 255, 16)
        float dep  = 2.0f + 0.5f * (float)tid;              // arange(2, 58, 0.5)

        float vx = xpix - scam[9];
        float vy = ypix - scam[10];
        float vz = dep  - scam[11];
        float ux = scam[0]*vx + scam[1]*vy + scam[2]*vz;
        float uy = scam[3]*vx + scam[4]*vy + scam[5]*vz;
        float uz = scam[6]*vx + scam[7]*vy + scam[8]*vz;
        float px = ux * uz, py = uy * uz, pz = uz;
        float gx = scam[12]*px + scam[13]*py + scam[14]*pz + scam[21];
        float gy = scam[15]*px + scam[16]*py + scam[17]*pz + scam[22];
        float gz = scam[18]*px + scam[19]*py + scam[20]*pz + scam[23];

        // match reference: lower = bx - dx/2, gi = int32((g - lower)/dx)
        const float dx0 = 0.8f, dx1 = 0.8f, dx2 = 20.0f;
        const float bx0 = -51.2f + 0.8f * 0.5f;
        const float bx1 = -51.2f + 0.8f * 0.5f;
        const float bx2 = -10.0f + 20.0f * 0.5f;
        int ix = (int)((gx - (bx0 - dx0 * 0.5f)) / dx0);
        int iy = (int)((gy - (bx1 - dx1 * 0.5f)) / dx1);
        int iz = (int)((gz - (bx2 - dx2 * 0.5f)) / dx2);

        if (ix >= 0 && ix < NXv && iy >= 0 && iy < NYv && iz == 0) {
            int p = atomicAdd(&cnt, 1);
            vlist[p] = ix * NYv + iy;
            plist[p] = e * inv_sum;
        }
    }
    __syncthreads();

    int total = cnt * CCH;
    for (int i = tid; i < total; i += 128) {
        int k = i / CCH;
        int c = i - k * CCH;
        atomicAdd(&out[c * (NXv * NYv) + vlist[k]], plist[k] * sfeat[c]);
    }
}

extern "C" void kernel_launch(void* const* d_in, const int* in_sizes, int n_in,
                              void* d_out, int out_size) {
    // inputs: x[0](unused), rots[1], trans[2], intrins[3], post_rots[4],
    //         post_trans[5], img_feat[6], depth_digit[7]
    const float* rots        = (const float*)d_in[1];
    const float* trans       = (const float*)d_in[2];
    const float* intrins     = (const float*)d_in[3];
    const float* post_rots   = (const float*)d_in[4];
    const float* post_trans  = (const float*)d_in[5];
    const float* img_feat    = (const float*)d_in[6];
    const float* depth_digit = (const float*)d_in[7];
    float* out = (float*)d_out;

    cudaMemsetAsync(out, 0, (size_t)out_size * sizeof(float));
    prep_cams<<<1, 32>>>(rots, trans, intrins, post_rots, post_trans);
    lss_scatter<<<NCAM * HFm * WFm, 128>>>(depth_digit, img_feat, out);
}

// round 3
// speedup vs baseline: 1.4957x; 1.4957x over previous
#include <cuda_runtime.h>
#include <cuda_bf16.h>
#include <math.h>

// ---- problem constants (BEVDepth config) ----
#define HFm 16
#define WFm 44
#define DEPTH 112
#define CCH 80
#define NCAM 6
#define NXv 128
#define NYv 128
#define HW (HFm * WFm)
#define NVOX (NXv * NYv)

// per-camera params: inv(post_rots)[9], post_trans[3], (rots@inv(intrins))[9], trans[3]
__device__ float g_cam[NCAM][24];
// voxel-major accumulation scratch: [voxel][channel], 5.24 MB
__device__ float g_scratch[NVOX * CCH];

__device__ __forceinline__ void inv3x3(const float* a, float* o) {
    float a00=a[0],a01=a[1],a02=a[2];
    float a10=a[3],a11=a[4],a12=a[5];
    float a20=a[6],a21=a[7],a22=a[8];
    float c00 =  (a11*a22 - a12*a21);
    float c01 = -(a10*a22 - a12*a20);
    float c02 =  (a10*a21 - a11*a20);
    float det = a00*c00 + a01*c01 + a02*c02;
    float id = 1.0f / det;
    o[0] =  (a11*a22 - a12*a21) * id;
    o[1] =  (a02*a21 - a01*a22) * id;
    o[2] =  (a01*a12 - a02*a11) * id;
    o[3] =  (a12*a20 - a10*a22) * id;
    o[4] =  (a00*a22 - a02*a20) * id;
    o[5] =  (a02*a10 - a00*a12) * id;
    o[6] =  (a10*a21 - a11*a20) * id;
    o[7] =  (a01*a20 - a00*a21) * id;
    o[8] =  (a00*a11 - a01*a10) * id;
}

__global__ void prep_cams(const float* __restrict__ rots,
                          const float* __restrict__ trans,
                          const float* __restrict__ intrins,
                          const float* __restrict__ post_rots,
                          const float* __restrict__ post_trans) {
    int n = threadIdx.x;
    if (n >= NCAM) return;
    float iP[9], iK[9];
    inv3x3(post_rots + n * 9, iP);
    inv3x3(intrins  + n * 9, iK);
    const float* R = rots + n * 9;
    float* cm = g_cam[n];
    #pragma unroll
    for (int i = 0; i < 9; i++) cm[i] = iP[i];
    #pragma unroll
    for (int i = 0; i < 3; i++) cm[9 + i] = post_trans[n * 3 + i];
    // M = R @ inv(K)
    #pragma unroll
    for (int i = 0; i < 3; i++)
        #pragma unroll
        for (int j = 0; j < 3; j++) {
            float s = 0.f;
            #pragma unroll
            for (int k = 0; k < 3; k++) s += R[i * 3 + k] * iK[k * 3 + j];
            cm[12 + i * 3 + j] = s;
        }
    #pragma unroll
    for (int i = 0; i < 3; i++) cm[21 + i] = trans[n * 3 + i];
}

// One block per camera ray (n, h, w). 128 threads.
// Fused: shfl softmax over D, geometry+validity, run-merge of consecutive
// depth bins hitting the same voxel, then v4 vectorized reductions into a
// voxel-major scratch buffer (contiguous lanes -> few L1tex wavefronts).
__global__ void __launch_bounds__(128)
lss_scatter(const float* __restrict__ depth_digit,
            const float* __restrict__ img_feat) {
    int idx = blockIdx.x;
    int w = idx % WFm;
    int h = (idx / WFm) % HFm;
    int n = idx / (WFm * HFm);
    int tid = threadIdx.x;
    int lane = tid & 31, warp = tid >> 5;

    __shared__ float sfeat[CCH];
    __shared__ float sp[DEPTH];
    __shared__ int   svox[128];
    __shared__ float plist[DEPTH];
    __shared__ int   vlist[DEPTH];
    __shared__ float scam[24];
    __shared__ float wred[4];
    __shared__ int   cnt;

    if (tid == 0) cnt = 0;
    if (tid < 24) scam[tid] = g_cam[n][tid];
    svox[tid] = -1;

    float myv = -1e30f;
    if (tid < DEPTH)
        myv = depth_digit[(n * DEPTH + tid) * HW + h * WFm + w];
    if (tid < CCH)
        sfeat[tid] = img_feat[(n * CCH + tid) * HW + h * WFm + w];

    // block max (shfl within warps, combine 4 partials)
    float m = myv;
    #pragma unroll
    for (int o = 16; o; o >>= 1) m = fmaxf(m, __shfl_xor_sync(0xffffffffu, m, o));
    if (lane == 0) wred[warp] = m;
    __syncthreads();
    m = fmaxf(fmaxf(wred[0], wred[1]), fmaxf(wred[2], wred[3]));
    __syncthreads();   // protect wred before reuse

    float e = (tid < DEPTH) ? __expf(myv - m) : 0.f;
    float s = e;
    #pragma unroll
    for (int o = 16; o; o >>= 1) s += __shfl_xor_sync(0xffffffffu, s, o);
    if (lane == 0) wred[warp] = s;
    __syncthreads();
    float inv_sum = 1.0f / (wred[0] + wred[1] + wred[2] + wred[3]);

    // geometry per depth bin
    if (tid < DEPTH) {
        float xpix = (float)((double)w * (703.0 / 43.0));  // linspace(0, 703, 44)
        float ypix = (float)h * 17.0f;                      // linspace(0, 255, 16)
        float dep  = 2.0f + 0.5f * (float)tid;              // arange(2, 58, 0.5)

        float vx = xpix - scam[9];
        float vy = ypix - scam[10];
        float vz = dep  - scam[11];
        float ux = scam[0]*vx + scam[1]*vy + scam[2]*vz;
        float uy = scam[3]*vx + scam[4]*vy + scam[5]*vz;
        float uz = scam[6]*vx + scam[7]*vy + scam[8]*vz;
        float px = ux * uz, py = uy * uz, pz = uz;
        float gx = scam[12]*px + scam[13]*py + scam[14]*pz + scam[21];
        float gy = scam[15]*px + scam[16]*py + scam[17]*pz + scam[22];
        float gz = scam[18]*px + scam[19]*py + scam[20]*pz + scam[23];

        // match reference: lower = bx - dx/2, gi = int32((g - lower)/dx)
        const float dx0 = 0.8f, dx1 = 0.8f, dx2 = 20.0f;
        const float bx0 = -51.2f + 0.8f * 0.5f;
        const float bx1 = -51.2f + 0.8f * 0.5f;
        const float bx2 = -10.0f + 20.0f * 0.5f;
        int ix = (int)((gx - (bx0 - dx0 * 0.5f)) / dx0);
        int iy = (int)((gy - (bx1 - dx1 * 0.5f)) / dx1);
        int iz = (int)((gz - (bx2 - dx2 * 0.5f)) / dx2);

        if (ix >= 0 && ix < NXv && iy >= 0 && iy < NYv && iz == 0)
            svox[tid] = ix * NYv + iy;
        sp[tid] = e * inv_sum;
    }
    __syncthreads();

    // merge runs of consecutive depth bins that land in the same voxel
    if (tid < DEPTH && svox[tid] >= 0 &&
        (tid == 0 || svox[tid - 1] != svox[tid])) {
        int vo = svox[tid];
        float acc = 0.f;
        int j = tid;
        while (j < DEPTH && svox[j] == vo) { acc += sp[j]; j++; }
        int p = atomicAdd(&cnt, 1);
        vlist[p] = vo;
        plist[p] = acc;
    }
    __syncthreads();

    // vectorized v4 reductions into voxel-major scratch
    int total = cnt * (CCH / 4);
    const float4* f4 = (const float4*)sfeat;
    for (int i = tid; i < total; i += 128) {
        int k = i / (CCH / 4);
        int q = i - k * (CCH / 4);
        float p = plist[k];
        float4 f = f4[q];
        float* dst = &g_scratch[vlist[k] * CCH + (q << 2)];
        asm volatile("red.global.add.v4.f32 [%0], {%1,%2,%3,%4};"
                     :: "l"(dst), "f"(p * f.x), "f"(p * f.y),
                        "f"(p * f.z), "f"(p * f.w)
                     : "memory");
    }
}

// scratch [voxel][channel]  ->  out [channel][voxel]  (shared-tile transpose)
__global__ void __launch_bounds__(256)
bev_transpose(float* __restrict__ out) {
    __shared__ float tile[32][CCH + 1];
    int v0 = blockIdx.x * 32;
    int tid = threadIdx.x;
    for (int i = tid; i < 32 * CCH; i += 256)
        tile[i / CCH][i % CCH] = g_scratch[v0 * CCH + i];
    __syncthreads();
    for (int i = tid; i < 32 * CCH; i += 256) {
        int c = i >> 5, vv = i & 31;
        out[c * NVOX + v0 + vv] = tile[vv][c];
    }
}

extern "C" void kernel_launch(void* const* d_in, const int* in_sizes, int n_in,
                              void* d_out, int out_size) {
    // inputs: x[0](unused), rots[1], trans[2], intrins[3], post_rots[4],
    //         post_trans[5], img_feat[6], depth_digit[7]
    const float* rots        = (const float*)d_in[1];
    const float* trans       = (const float*)d_in[2];
    const float* intrins     = (const float*)d_in[3];
    const float* post_rots   = (const float*)d_in[4];
    const float* post_trans  = (const float*)d_in[5];
    const float* img_feat    = (const float*)d_in[6];
    const float* depth_digit = (const float*)d_in[7];
    float* out = (float*)d_out;

    void* scratch_ptr = nullptr;
    cudaGetSymbolAddress(&scratch_ptr, g_scratch);
    cudaMemsetAsync(scratch_ptr, 0, sizeof(float) * NVOX * CCH);

    prep_cams<<<1, 32>>>(rots, trans, intrins, post_rots, post_trans);
    lss_scatter<<<NCAM * HW, 128>>>(depth_digit, img_feat);
    bev_transpose<<<NVOX / 32, 256>>>(out);
}

// round 4
// speedup vs baseline: 2.6396x; 1.7648x over previous
#include <cuda_runtime.h>
#include <cuda_bf16.h>
#include <math.h>

// ---- problem constants (BEVDepth config) ----
#define HFm 16
#define WFm 44
#define DEPTH 112
#define CCH 80
#define NCAM 6
#define NXv 128
#define NYv 128
#define HW (HFm * WFm)
#define NVOX (NXv * NYv)

// voxel-major accumulation scratch: [voxel][channel], 5.24 MB
// Zero-initialized at module load; bev_transpose re-zeroes after each read,
// so every kernel_launch execution starts from a clean scratch.
__device__ float g_scratch[NVOX * CCH];

__device__ __forceinline__ void inv3x3(const float* a, float* o) {
    float a00=a[0],a01=a[1],a02=a[2];
    float a10=a[3],a11=a[4],a12=a[5];
    float a20=a[6],a21=a[7],a22=a[8];
    float det = a00*(a11*a22 - a12*a21)
              - a01*(a10*a22 - a12*a20)
              + a02*(a10*a21 - a11*a20);
    float id = 1.0f / det;
    o[0] =  (a11*a22 - a12*a21) * id;
    o[1] =  (a02*a21 - a01*a22) * id;
    o[2] =  (a01*a12 - a02*a11) * id;
    o[3] =  (a12*a20 - a10*a22) * id;
    o[4] =  (a00*a22 - a02*a20) * id;
    o[5] =  (a02*a10 - a00*a12) * id;
    o[6] =  (a10*a21 - a11*a20) * id;
    o[7] =  (a01*a20 - a00*a21) * id;
    o[8] =  (a00*a11 - a01*a10) * id;
}

// One block per camera ray (n, h, w). 128 threads.
// Fused: inline camera-matrix prep (thread 0, hidden under loads),
// shfl softmax over D, geometry+validity, run-merge of consecutive depth
// bins hitting the same voxel, v4 vectorized reductions into voxel-major
// scratch (contiguous lanes -> few L1tex wavefronts).
__global__ void __launch_bounds__(128)
lss_scatter(const float* __restrict__ depth_digit,
            const float* __restrict__ img_feat,
            const float* __restrict__ rots,
            const float* __restrict__ trans,
            const float* __restrict__ intrins,
            const float* __restrict__ post_rots,
            const float* __restrict__ post_trans) {
    int idx = blockIdx.x;
    int w = idx % WFm;
    int h = (idx / WFm) % HFm;
    int n = idx / (WFm * HFm);
    int tid = threadIdx.x;
    int lane = tid & 31, warp = tid >> 5;

    __shared__ float sfeat[CCH];
    __shared__ float sp[DEPTH];
    __shared__ int   svox[128];
    __shared__ float plist[DEPTH];
    __shared__ int   vlist[DEPTH];
    __shared__ float scam[24];
    __shared__ float wred[4];
    __shared__ int   cnt;

    if (tid == 0) cnt = 0;
    svox[tid] = -1;

    // issue global loads first so the cam-matrix math below overlaps them
    float myv = -1e30f;
    if (tid < DEPTH)
        myv = depth_digit[(n * DEPTH + tid) * HW + h * WFm + w];
    if (tid < CCH)
        sfeat[tid] = img_feat[(n * CCH + tid) * HW + h * WFm + w];

    // inline per-camera parameter computation (tiny, redundant per block)
    if (tid == 0) {
        float iP[9], iK[9];
        inv3x3(post_rots + n * 9, iP);
        inv3x3(intrins  + n * 9, iK);
        const float* R = rots + n * 9;
        #pragma unroll
        for (int i = 0; i < 9; i++) scam[i] = iP[i];
        #pragma unroll
        for (int i = 0; i < 3; i++) scam[9 + i] = post_trans[n * 3 + i];
        #pragma unroll
        for (int i = 0; i < 3; i++)
            #pragma unroll
            for (int j = 0; j < 3; j++) {
                float s = 0.f;
                #pragma unroll
                for (int k = 0; k < 3; k++) s += R[i * 3 + k] * iK[k * 3 + j];
                scam[12 + i * 3 + j] = s;
            }
        #pragma unroll
        for (int i = 0; i < 3; i++) scam[21 + i] = trans[n * 3 + i];
    }

    // block max (shfl within warps, combine 4 partials)
    float m = myv;
    #pragma unroll
    for (int o = 16; o; o >>= 1) m = fmaxf(m, __shfl_xor_sync(0xffffffffu, m, o));
    if (lane == 0) wred[warp] = m;
    __syncthreads();
    m = fmaxf(fmaxf(wred[0], wred[1]), fmaxf(wred[2], wred[3]));
    __syncthreads();   // protect wred before reuse

    float e = (tid < DEPTH) ? __expf(myv - m) : 0.f;
    float s = e;
    #pragma unroll
    for (int o = 16; o; o >>= 1) s += __shfl_xor_sync(0xffffffffu, s, o);
    if (lane == 0) wred[warp] = s;
    __syncthreads();
    float inv_sum = 1.0f / (wred[0] + wred[1] + wred[2] + wred[3]);

    // geometry per depth bin
    if (tid < DEPTH) {
        float xpix = (float)((double)w * (703.0 / 43.0));  // linspace(0, 703, 44)
        float ypix = (float)h * 17.0f;                      // linspace(0, 255, 16)
        float dep  = 2.0f + 0.5f * (float)tid;              // arange(2, 58, 0.5)

        float vx = xpix - scam[9];
        float vy = ypix - scam[10];
        float vz = dep  - scam[11];
        float ux = scam[0]*vx + scam[1]*vy + scam[2]*vz;
        float uy = scam[3]*vx + scam[4]*vy + scam[5]*vz;
        float uz = scam[6]*vx + scam[7]*vy + scam[8]*vz;
        float px = ux * uz, py = uy * uz, pz = uz;
        float gx = scam[12]*px + scam[13]*py + scam[14]*pz + scam[21];
        float gy = scam[15]*px + scam[16]*py + scam[17]*pz + scam[22];
        float gz = scam[18]*px + scam[19]*py + scam[20]*pz + scam[23];

        // match reference: lower = bx - dx/2, gi = int32((g - lower)/dx)
        const float dx0 = 0.8f, dx1 = 0.8f, dx2 = 20.0f;
        const float bx0 = -51.2f + 0.8f * 0.5f;
        const float bx1 = -51.2f + 0.8f * 0.5f;
        const float bx2 = -10.0f + 20.0f * 0.5f;
        int ix = (int)((gx - (bx0 - dx0 * 0.5f)) / dx0);
        int iy = (int)((gy - (bx1 - dx1 * 0.5f)) / dx1);
        int iz = (int)((gz - (bx2 - dx2 * 0.5f)) / dx2);

        if (ix >= 0 && ix < NXv && iy >= 0 && iy < NYv && iz == 0)
            svox[tid] = ix * NYv + iy;
        sp[tid] = e * inv_sum;
    }
    __syncthreads();

    // merge runs of consecutive depth bins that land in the same voxel
    if (tid < DEPTH && svox[tid] >= 0 &&
        (tid == 0 || svox[tid - 1] != svox[tid])) {
        int vo = svox[tid];
        float acc = 0.f;
        int j = tid;
        while (j < DEPTH && svox[j] == vo) { acc += sp[j]; j++; }
        int p = atomicAdd(&cnt, 1);
        vlist[p] = vo;
        plist[p] = acc;
    }
    __syncthreads();

    // vectorized v4 reductions into voxel-major scratch
    int total = cnt * (CCH / 4);
    const float4* f4 = (const float4*)sfeat;
    for (int i = tid; i < total; i += 128) {
        int k = i / (CCH / 4);
        int q = i - k * (CCH / 4);
        float p = plist[k];
        float4 f = f4[q];
        float* dst = &g_scratch[vlist[k] * CCH + (q << 2)];
        asm volatile("red.global.add.v4.f32 [%0], {%1,%2,%3,%4};"
                     :: "l"(dst), "f"(p * f.x), "f"(p * f.y),
                        "f"(p * f.z), "f"(p * f.w)
                     : "memory");
    }
}

// scratch [voxel][channel] -> out [channel][voxel] (shared-tile transpose),
// then re-zero the scratch slice so the next replay starts clean.
__global__ void __launch_bounds__(256)
bev_transpose(float* __restrict__ out) {
    __shared__ float tile[32][CCH + 1];
    int v0 = blockIdx.x * 32;
    int tid = threadIdx.x;
    float4* s4 = (float4*)&g_scratch[v0 * CCH];
    for (int i = tid; i < 32 * CCH / 4; i += 256) {
        float4 v = s4[i];
        int base = i << 2;
        int r = base / CCH, c = base % CCH;
        tile[r][c] = v.x; tile[r][c+1] = v.y; tile[r][c+2] = v.z; tile[r][c+3] = v.w;
    }
    __syncthreads();
    // re-zero scratch slice (exclusive to this block)
    float4 z = make_float4(0.f, 0.f, 0.f, 0.f);
    for (int i = tid; i < 32 * CCH / 4; i += 256) s4[i] = z;
    for (int i = tid; i < 32 * CCH; i += 256) {
        int c = i >> 5, vv = i & 31;
        out[c * NVOX + v0 + vv] = tile[vv][c];
    }
}

extern "C" void kernel_launch(void* const* d_in, const int* in_sizes, int n_in,
                              void* d_out, int out_size) {
    // inputs: x[0](unused), rots[1], trans[2], intrins[3], post_rots[4],
    //         post_trans[5], img_feat[6], depth_digit[7]
    const float* rots        = (const float*)d_in[1];
    const float* trans       = (const float*)d_in[2];
    const float* intrins     = (const float*)d_in[3];
    const float* post_rots   = (const float*)d_in[4];
    const float* post_trans  = (const float*)d_in[5];
    const float* img_feat    = (const float*)d_in[6];
    const float* depth_digit = (const float*)d_in[7];
    float* out = (float*)d_out;

    lss_scatter<<<NCAM * HW, 128>>>(depth_digit, img_feat,
                                    rots, trans, intrins, post_rots, post_trans);
    bev_transpose<<<NVOX / 32, 256>>>(out);
}